// round 15
// baseline (speedup 1.0000x reference)
#include <cuda_runtime.h>
#include <cuda_bf16.h>

// out[i] = (|bits[i % 4096]| > 0.5) ? 1.0f : 0.0f for all 48*1024*1024 elements.
// Derivation: within a channel, idx = (x*WIDTH + y) % 4096 = j % 4096; the
// channel stride 1024*1024 is an exact multiple of 4096, so one 4096-float
// pattern tiles the entire (48,1024,1024) output 12288 times.
//
// R2 evidence: LTS-bound at ~6.2 TB/s effective store rate (~ chip cap).
// This round removes the SMEM prologue/barrier: each thread loads its 16
// pattern values directly from global (L2-broadcast hot) into registers.

#define PATTERN_FLOATS 4096
#define PATTERN_VEC4   1024          // 4096 floats = 1024 float4
#define THREADS        256
#define BLOCKS         1184          // 148 SMs * 8 CTAs, one resident wave

__device__ __forceinline__ float4 thresh4(float4 b) {
    float4 r;
    r.x = (fabsf(b.x) > 0.5f) ? 1.0f : 0.0f;
    r.y = (fabsf(b.y) > 0.5f) ? 1.0f : 0.0f;
    r.z = (fabsf(b.z) > 0.5f) ? 1.0f : 0.0f;
    r.w = (fabsf(b.w) > 0.5f) ? 1.0f : 0.0f;
    return r;
}

__global__ __launch_bounds__(THREADS) void pattern_broadcast_kernel(
    const float4* __restrict__ bits4,   // 1024 float4 = 4096 floats
    float4* __restrict__ out,
    int n_chunks)                       // out_size / 4096 = 12288
{
    const int t = threadIdx.x;

    // Register-resident pattern: thread t owns vec4 slots t, t+256, t+512,
    // t+768 of the 1024-float4 pattern. 4 independent LDG.128, no SMEM,
    // no barrier.
    const float4 v0 = thresh4(bits4[t]);
    const float4 v1 = thresh4(bits4[t + 256]);
    const float4 v2 = thresh4(bits4[t + 512]);
    const float4 v3 = thresh4(bits4[t + 768]);

    // Grid-stride over pattern-sized chunks, 2 chunks per iteration
    // (8 independent STG.128 in flight per thread).
    int c = blockIdx.x;
    const int stride = gridDim.x;
    for (; c + stride < n_chunks; c += 2 * stride) {
        float4* o0 = out + (size_t)c * PATTERN_VEC4;
        float4* o1 = out + (size_t)(c + stride) * PATTERN_VEC4;
        o0[t]       = v0;
        o0[t + 256] = v1;
        o0[t + 512] = v2;
        o0[t + 768] = v3;
        o1[t]       = v0;
        o1[t + 256] = v1;
        o1[t + 512] = v2;
        o1[t + 768] = v3;
    }
    if (c < n_chunks) {
        float4* o = out + (size_t)c * PATTERN_VEC4;
        o[t]       = v0;
        o[t + 256] = v1;
        o[t + 512] = v2;
        o[t + 768] = v3;
    }
}

extern "C" void kernel_launch(void* const* d_in, const int* in_sizes, int n_in,
                              void* d_out, int out_size) {
    const float4* bits4 = (const float4*)d_in[0];
    float4* out = (float4*)d_out;

    int n_chunks = out_size / PATTERN_FLOATS;   // 12288

    pattern_broadcast_kernel<<<BLOCKS, THREADS>>>(bits4, out, n_chunks);
}